// round 2
// baseline (speedup 1.0000x reference)
#include <cuda_runtime.h>

// Problem constants
#define TS    1536     // sequence length
#define TDM   2880     // model dim
#define THQ   64       // query heads
#define THKV  8        // kv heads
#define TDH   64       // head dim
#define TNREP 8        // HQ / HKV
#define TQD   4096     // HQ*DH
#define TKD   512      // HKV*DH
#define TSCALE 0.125f

static const long OUT_ELEMS  = (long)TS * TDM;        // 4,423,680
static const long ATTN_ELEMS = (long)THQ * TS * TS;   // 150,994,944

// Scratch (device globals: allocation-free per harness rules)
__device__ float g_Qlin[(size_t)TS * TQD];
__device__ float g_Klin[(size_t)TS * TKD];
__device__ float g_Vlin[(size_t)TS * TKD];
__device__ float g_Opre[(size_t)TS * TQD];
__device__ float g_attn_scratch[(size_t)THQ * TS * TS];  // only used if out buffer lacks attn

// ---------------------------------------------------------------------------
// Generic batched tiled SGEMM: C[m,n] = sum_k A[m,k] * B(k,n) (+ bias[n])
//   tn=1: B is [N,K] row-major  (dot of rows, "TN")
//   tn=0: B is [K,N] row-major  ("NN")
// Batch z: A += z*sA; B += (z/bGroup)*sB; C += z*sC   (bGroup handles GQA)
// Tiles: BM=128, BN=64, BK=8. 256 threads, 8x4 per-thread register tile.
// Requires: M%128==0, N%64==0, K%8==0, all pointers/lds 16B-friendly.
// ---------------------------------------------------------------------------
__global__ __launch_bounds__(256) void gemm_tiled(
    const float* __restrict__ A, const float* __restrict__ B,
    const float* __restrict__ bias, float* __restrict__ C,
    int M, int N, int K, int lda, int ldb, int ldc,
    long sA, long sB, long sC, int bGroup, int tn)
{
    int z = blockIdx.z;
    A += (long)z * sA;
    B += (long)(z / bGroup) * sB;
    C += (long)z * sC;

    __shared__ float As[8][128];
    __shared__ float Bs[8][64];

    int t  = threadIdx.x;
    int tx = t & 15, ty = t >> 4;
    int m0 = blockIdx.y * 128;
    int n0 = blockIdx.x * 64;

    float acc[8][4];
#pragma unroll
    for (int i = 0; i < 8; i++)
#pragma unroll
        for (int j = 0; j < 4; j++) acc[i][j] = 0.f;

    for (int k0 = 0; k0 < K; k0 += 8) {
        // A tile: 128x8, one float4 per thread
        {
            int m = t >> 1, kk = (t & 1) * 4;
            float4 v = *reinterpret_cast<const float4*>(A + (long)(m0 + m) * lda + k0 + kk);
            As[kk + 0][m] = v.x; As[kk + 1][m] = v.y;
            As[kk + 2][m] = v.z; As[kk + 3][m] = v.w;
        }
        // B tile: 64x8 (TN) or 8x64 (NN), threads 0..127
        if (t < 128) {
            if (tn) {
                int n = t >> 1, kk = (t & 1) * 4;
                float4 v = *reinterpret_cast<const float4*>(B + (long)(n0 + n) * ldb + k0 + kk);
                Bs[kk + 0][n] = v.x; Bs[kk + 1][n] = v.y;
                Bs[kk + 2][n] = v.z; Bs[kk + 3][n] = v.w;
            } else {
                int kk = t >> 4, nv = (t & 15) * 4;
                float4 v = *reinterpret_cast<const float4*>(B + (long)(k0 + kk) * ldb + n0 + nv);
                *reinterpret_cast<float4*>(&Bs[kk][nv]) = v;
            }
        }
        __syncthreads();
#pragma unroll
        for (int kk = 0; kk < 8; kk++) {
            float a[8], b[4];
#pragma unroll
            for (int i = 0; i < 8; i++) a[i] = As[kk][ty + 16 * i];
#pragma unroll
            for (int j = 0; j < 4; j++) b[j] = Bs[kk][tx + 16 * j];
#pragma unroll
            for (int i = 0; i < 8; i++)
#pragma unroll
                for (int j = 0; j < 4; j++) acc[i][j] += a[i] * b[j];
        }
        __syncthreads();
    }

#pragma unroll
    for (int i = 0; i < 8; i++) {
        long m = m0 + ty + 16 * i;
#pragma unroll
        for (int j = 0; j < 4; j++) {
            int n = n0 + tx + 16 * j;
            float v = acc[i][j];
            if (bias) v += bias[n];
            C[m * ldc + n] = v;
        }
    }
}

// ---------------------------------------------------------------------------
// RoPE (half-split variant) applied in place to Q [S, HQ*DH] and K [S, HKV*DH]
// ---------------------------------------------------------------------------
__global__ void rope_kernel(float* __restrict__ Qlin, float* __restrict__ Klin,
                            const float* __restrict__ cosv, const float* __restrict__ sinv)
{
    int idx = blockIdx.x * blockDim.x + threadIdx.x;
    const int total = TS * (THQ + THKV) * (TDH / 2);
    if (idx >= total) return;
    int d  = idx & 31;
    int hh = (idx >> 5) % (THQ + THKV);
    int s  = idx / ((THQ + THKV) * 32);
    float c  = cosv[s * 32 + d];
    float sn = sinv[s * 32 + d];
    float* p = (hh < THQ) ? (Qlin + (long)s * TQD + hh * TDH)
                          : (Klin + (long)s * TKD + (hh - THQ) * TDH);
    float x1 = p[d], x2 = p[d + 32];
    p[d]      = x1 * c - x2 * sn;
    p[d + 32] = x2 * c + x1 * sn;
}

// ---------------------------------------------------------------------------
// Causal softmax with sink column, in place over raw scores.
// Row = attn[h][q][:]; valid k <= q. Writes exact 0 for k > q.
// ---------------------------------------------------------------------------
__global__ __launch_bounds__(256) void softmax_kernel(float* __restrict__ attn,
                                                      const float* __restrict__ sinks)
{
    int q = blockIdx.x, h = blockIdx.y;
    float* row = attn + ((long)h * TS + q) * TS;
    int t = threadIdx.x;
    __shared__ float red[256];

    float m = -3.0e38f;
    for (int k = t; k <= q; k += 256) m = fmaxf(m, row[k] * TSCALE);
    red[t] = m; __syncthreads();
    for (int s = 128; s > 0; s >>= 1) {
        if (t < s) red[t] = fmaxf(red[t], red[t + s]);
        __syncthreads();
    }
    float sink = sinks[h];
    float mx = fmaxf(red[0], sink);
    __syncthreads();

    float sum = 0.f;
    for (int k = t; k <= q; k += 256) sum += expf(row[k] * TSCALE - mx);
    red[t] = sum; __syncthreads();
    for (int s = 128; s > 0; s >>= 1) {
        if (t < s) red[t] += red[t + s];
        __syncthreads();
    }
    float inv = 1.f / (red[0] + expf(sink - mx));
    __syncthreads();

    for (int k = t; k < TS; k += 256)
        row[k] = (k <= q) ? expf(row[k] * TSCALE - mx) * inv : 0.f;
}

// ---------------------------------------------------------------------------
extern "C" void kernel_launch(void* const* d_in, const int* in_sizes, int n_in,
                              void* d_out, int out_size)
{
    (void)in_sizes; (void)n_in;
    const float* X     = (const float*)d_in[0];
    // d_in[1] = attention_mask (pure causal; reproduced analytically)
    const float* cosv  = (const float*)d_in[2];
    const float* sinv  = (const float*)d_in[3];
    const float* Wq    = (const float*)d_in[4];
    const float* bq    = (const float*)d_in[5];
    const float* Wk    = (const float*)d_in[6];
    const float* bk    = (const float*)d_in[7];
    const float* Wv    = (const float*)d_in[8];
    const float* bv    = (const float*)d_in[9];
    const float* Wo    = (const float*)d_in[10];
    const float* bo    = (const float*)d_in[11];
    const float* sinks = (const float*)d_in[12];

    float *Qlin, *Klin, *Vlin, *Opre, *attnScr;
    cudaGetSymbolAddress((void**)&Qlin, g_Qlin);
    cudaGetSymbolAddress((void**)&Klin, g_Klin);
    cudaGetSymbolAddress((void**)&Vlin, g_Vlin);
    cudaGetSymbolAddress((void**)&Opre, g_Opre);
    cudaGetSymbolAddress((void**)&attnScr, g_attn_scratch);

    float* out  = (float*)d_out;
    float* attn = ((long)out_size >= OUT_ELEMS + ATTN_ELEMS) ? (out + OUT_ELEMS) : attnScr;

    dim3 blk(256);

    // 1-3) QKV projections: [S,DM] x [N,DM]^T + bias
    gemm_tiled<<<dim3(TQD / 64, TS / 128, 1), blk>>>(X, Wq, bq, Qlin,
        TS, TQD, TDM, TDM, TDM, TQD, 0, 0, 0, 1, 1);
    gemm_tiled<<<dim3(TKD / 64, TS / 128, 1), blk>>>(X, Wk, bk, Klin,
        TS, TKD, TDM, TDM, TDM, TKD, 0, 0, 0, 1, 1);
    gemm_tiled<<<dim3(TKD / 64, TS / 128, 1), blk>>>(X, Wv, bv, Vlin,
        TS, TKD, TDM, TDM, TDM, TKD, 0, 0, 0, 1, 1);

    // 4) RoPE on Q and K
    {
        int np = TS * (THQ + THKV) * (TDH / 2);
        rope_kernel<<<(np + 255) / 256, 256>>>(Qlin, Klin, cosv, sinv);
    }

    // 5) Raw scores per head: S[h][q][k] = Q_h[q,:] . K_kv[k,:]   (TN, batched)
    gemm_tiled<<<dim3(TS / 64, TS / 128, THQ), blk>>>(Qlin, Klin, nullptr, attn,
        TS, TS, TDH, TQD, TKD, TS,
        /*sA=*/TDH, /*sB=*/TDH, /*sC=*/(long)TS * TS, /*bGroup=*/TNREP, /*tn=*/1);

    // 6) Softmax with sink (in place -> attention probs, zeros above diagonal)
    softmax_kernel<<<dim3(TS, THQ), 256>>>(attn, sinks);

    // 7) attn @ V per head: Opre[q, h*64+d] = sum_k P[h][q][k] * V_kv[k][d]  (NN, batched)
    gemm_tiled<<<dim3(TDH / 64, TS / 128, THQ), blk>>>(attn, Vlin, nullptr, Opre,
        TS, TDH, TS, TS, TKD, TQD,
        /*sA=*/(long)TS * TS, /*sB=*/TDH, /*sC=*/TDH, /*bGroup=*/TNREP, /*tn=*/0);

    // 8) Output projection: out = Opre x Wo^T + bo
    gemm_tiled<<<dim3(TDM / 64, TS / 128, 1), blk>>>(Opre, Wo, bo, out,
        TS, TDM, TQD, TQD, TQD, TDM, 0, 0, 0, 1, 1);
}

// round 6
// speedup vs baseline: 1.6955x; 1.6955x over previous
#include <cuda_runtime.h>
#include <cuda_bf16.h>
#include <cstdint>
#include <cfloat>

// ---------------- problem constants ----------------
#define TS    1536
#define TDM   2880
#define THQ   64
#define THKV  8
#define TDH   64
#define TNREP 8
#define TQD   4096
#define TKD   512
#define TSCALE 0.125f

static const long OUT_ELEMS  = (long)TS * TDM;
static const long ATTN_ELEMS = (long)THQ * TS * TS;

// ---------------- device scratch (allocation-free) ----------------
__device__ __align__(1024) float g_Qlin[(size_t)TS * TQD];
__device__ __align__(1024) float g_Klin[(size_t)TS * TKD];
__device__ __align__(1024) float g_Vlin[(size_t)TS * TKD];
__device__ __align__(1024) float g_Opre[(size_t)TS * TQD];
__device__ __align__(1024) float g_attn_scratch[(size_t)THQ * TS * TS];

__device__ __align__(1024) __nv_bfloat16 g_Xh[(size_t)TS * TDM];
__device__ __align__(1024) __nv_bfloat16 g_Xl[(size_t)TS * TDM];
__device__ __align__(1024) __nv_bfloat16 g_Wqh[(size_t)TQD * TDM];
__device__ __align__(1024) __nv_bfloat16 g_Wql[(size_t)TQD * TDM];
__device__ __align__(1024) __nv_bfloat16 g_Wkh[(size_t)TKD * TDM];
__device__ __align__(1024) __nv_bfloat16 g_Wkl[(size_t)TKD * TDM];
__device__ __align__(1024) __nv_bfloat16 g_Wvh[(size_t)TKD * TDM];
__device__ __align__(1024) __nv_bfloat16 g_Wvl[(size_t)TKD * TDM];
__device__ __align__(1024) __nv_bfloat16 g_Woh[(size_t)TDM * TQD];
__device__ __align__(1024) __nv_bfloat16 g_Wol[(size_t)TDM * TQD];
__device__ __align__(1024) __nv_bfloat16 g_Oh[(size_t)TS * TQD];
__device__ __align__(1024) __nv_bfloat16 g_Ol[(size_t)TS * TQD];

// ============================================================================
// VERIFIED R2 FFMA GEMM (passed at rel_err 1e-6) — used for scores & attn@V
// ============================================================================
__global__ __launch_bounds__(256) void gemm_tiled(
    const float* __restrict__ A, const float* __restrict__ B,
    const float* __restrict__ bias, float* __restrict__ C,
    int M, int N, int K, int lda, int ldb, int ldc,
    long sA, long sB, long sC, int bGroup, int tn)
{
    int z = blockIdx.z;
    A += (long)z * sA;
    B += (long)(z / bGroup) * sB;
    C += (long)z * sC;

    __shared__ float As[8][128];
    __shared__ float Bs[8][64];

    int t  = threadIdx.x;
    int tx = t & 15, ty = t >> 4;
    int m0 = blockIdx.y * 128;
    int n0 = blockIdx.x * 64;

    float acc[8][4];
#pragma unroll
    for (int i = 0; i < 8; i++)
#pragma unroll
        for (int j = 0; j < 4; j++) acc[i][j] = 0.f;

    for (int k0 = 0; k0 < K; k0 += 8) {
        {
            int m = t >> 1, kk = (t & 1) * 4;
            float4 v = *reinterpret_cast<const float4*>(A + (long)(m0 + m) * lda + k0 + kk);
            As[kk + 0][m] = v.x; As[kk + 1][m] = v.y;
            As[kk + 2][m] = v.z; As[kk + 3][m] = v.w;
        }
        if (t < 128) {
            if (tn) {
                int n = t >> 1, kk = (t & 1) * 4;
                float4 v = *reinterpret_cast<const float4*>(B + (long)(n0 + n) * ldb + k0 + kk);
                Bs[kk + 0][n] = v.x; Bs[kk + 1][n] = v.y;
                Bs[kk + 2][n] = v.z; Bs[kk + 3][n] = v.w;
            } else {
                int kk = t >> 4, nv = (t & 15) * 4;
                float4 v = *reinterpret_cast<const float4*>(B + (long)(k0 + kk) * ldb + n0 + nv);
                *reinterpret_cast<float4*>(&Bs[kk][nv]) = v;
            }
        }
        __syncthreads();
#pragma unroll
        for (int kk = 0; kk < 8; kk++) {
            float a[8], b[4];
#pragma unroll
            for (int i = 0; i < 8; i++) a[i] = As[kk][ty + 16 * i];
#pragma unroll
            for (int j = 0; j < 4; j++) b[j] = Bs[kk][tx + 16 * j];
#pragma unroll
            for (int i = 0; i < 8; i++)
#pragma unroll
                for (int j = 0; j < 4; j++) acc[i][j] += a[i] * b[j];
        }
        __syncthreads();
    }

#pragma unroll
    for (int i = 0; i < 8; i++) {
        long m = m0 + ty + 16 * i;
#pragma unroll
        for (int j = 0; j < 4; j++) {
            int n = n0 + tx + 16 * j;
            float v = acc[i][j];
            if (bias) v += bias[n];
            C[m * ldc + n] = v;
        }
    }
}

// ============================================================================
// mma.sync bf16 GEMM (under test) — used for QKV + out-proj only this round
// ============================================================================
__device__ __forceinline__ void mma16816(float* d, const uint32_t* a, uint32_t b0, uint32_t b1) {
    asm volatile(
        "mma.sync.aligned.m16n8k16.row.col.f32.bf16.bf16.f32 "
        "{%0,%1,%2,%3}, {%4,%5,%6,%7}, {%8,%9}, {%0,%1,%2,%3};"
        : "+f"(d[0]), "+f"(d[1]), "+f"(d[2]), "+f"(d[3])
        : "r"(a[0]), "r"(a[1]), "r"(a[2]), "r"(a[3]), "r"(b0), "r"(b1));
}

#define SRP 72

__global__ __launch_bounds__(256)
void gemm_tc(const __nv_bfloat16* __restrict__ Ah, const __nv_bfloat16* __restrict__ Al,
             const __nv_bfloat16* __restrict__ Bh, const __nv_bfloat16* __restrict__ Bl,
             const float* __restrict__ bias, float* __restrict__ C,
             int K, int lda, int ldb, int ldc,
             long sA, long sB, long sC, int bGroup, int nsplit)
{
    __shared__ __align__(16) __nv_bfloat16 smA[128 * SRP];
    __shared__ __align__(16) __nv_bfloat16 smB[64 * SRP];

    const int z = blockIdx.z;
    const __nv_bfloat16* PA[3];
    const __nv_bfloat16* PB[3];
    {
        const __nv_bfloat16* ah = Ah + (long)z * sA;
        const __nv_bfloat16* bh = Bh + (long)(z / bGroup) * sB;
        const __nv_bfloat16* al = (nsplit == 3) ? (Al + (long)z * sA) : ah;
        const __nv_bfloat16* bl = (nsplit == 3) ? (Bl + (long)(z / bGroup) * sB) : bh;
        PA[0] = ah; PA[1] = ah; PA[2] = al;
        PB[0] = bh; PB[1] = bl; PB[2] = bh;
    }

    const int t    = threadIdx.x;
    const int lane = t & 31;
    const int w    = t >> 5;
    const int wm   = (w >> 1) * 32;
    const int wn   = (w & 1) * 32;
    const int g    = lane >> 2;
    const int tg   = lane & 3;
    const int m0   = blockIdx.y * 128;
    const int n0   = blockIdx.x * 64;

    const int ncK = K >> 6;
    const int nc  = ncK * nsplit;

    float acc[2][4][4];
#pragma unroll
    for (int i = 0; i < 2; i++)
#pragma unroll
        for (int j = 0; j < 4; j++)
#pragma unroll
            for (int e = 0; e < 4; e++) acc[i][j][e] = 0.f;

    uint4 va[4], vb[2];
    int kcL = 0, phL = 0;

    {
        const __nv_bfloat16* pa = PA[0];
        const __nv_bfloat16* pb = PB[0];
#pragma unroll
        for (int i = 0; i < 4; ++i) {
            int ch = t + 256 * i;
            va[i] = *reinterpret_cast<const uint4*>(pa + (long)(m0 + (ch >> 3)) * lda + (long)(ch & 7) * 8);
        }
#pragma unroll
        for (int j = 0; j < 2; ++j) {
            int ch = t + 256 * j;
            vb[j] = *reinterpret_cast<const uint4*>(pb + (long)(n0 + (ch >> 3)) * ldb + (long)(ch & 7) * 8);
        }
        if (++kcL == ncK) { kcL = 0; ++phL; }
    }

    for (int c = 0; c < nc; ++c) {
        __syncthreads();
#pragma unroll
        for (int i = 0; i < 4; ++i) {
            int ch = t + 256 * i;
            *reinterpret_cast<uint4*>(smA + (ch >> 3) * SRP + (ch & 7) * 8) = va[i];
        }
#pragma unroll
        for (int j = 0; j < 2; ++j) {
            int ch = t + 256 * j;
            *reinterpret_cast<uint4*>(smB + (ch >> 3) * SRP + (ch & 7) * 8) = vb[j];
        }
        __syncthreads();

        if (c + 1 < nc) {
            const __nv_bfloat16* pa = PA[phL];
            const __nv_bfloat16* pb = PB[phL];
            const long k0 = (long)kcL << 6;
#pragma unroll
            for (int i = 0; i < 4; ++i) {
                int ch = t + 256 * i;
                va[i] = *reinterpret_cast<const uint4*>(pa + (long)(m0 + (ch >> 3)) * lda + k0 + (long)(ch & 7) * 8);
            }
#pragma unroll
            for (int j = 0; j < 2; ++j) {
                int ch = t + 256 * j;
                vb[j] = *reinterpret_cast<const uint4*>(pb + (long)(n0 + (ch >> 3)) * ldb + k0 + (long)(ch & 7) * 8);
            }
            if (++kcL == ncK) { kcL = 0; ++phL; }
        }

#pragma unroll
        for (int ks = 0; ks < 4; ++ks) {
            const int kk = ks * 16;
            uint32_t a[2][4];
#pragma unroll
            for (int mi = 0; mi < 2; ++mi) {
                const __nv_bfloat16* p0 = smA + (wm + mi * 16 + g) * SRP + kk + tg * 2;
                a[mi][0] = *reinterpret_cast<const uint32_t*>(p0);
                a[mi][1] = *reinterpret_cast<const uint32_t*>(p0 + 8 * SRP);
                a[mi][2] = *reinterpret_cast<const uint32_t*>(p0 + 8);
                a[mi][3] = *reinterpret_cast<const uint32_t*>(p0 + 8 * SRP + 8);
            }
            uint32_t b0[4], b1[4];
#pragma unroll
            for (int j = 0; j < 4; ++j) {
                const __nv_bfloat16* p0 = smB + (wn + j * 8 + g) * SRP + kk + tg * 2;
                b0[j] = *reinterpret_cast<const uint32_t*>(p0);
                b1[j] = *reinterpret_cast<const uint32_t*>(p0 + 8);
            }
#pragma unroll
            for (int mi = 0; mi < 2; ++mi)
#pragma unroll
                for (int j = 0; j < 4; ++j)
                    mma16816(acc[mi][j], a[mi], b0[j], b1[j]);
        }
    }

#pragma unroll
    for (int mi = 0; mi < 2; ++mi) {
        long row0 = m0 + wm + mi * 16 + g;
#pragma unroll
        for (int j = 0; j < 4; ++j) {
            int col = n0 + wn + j * 8 + tg * 2;
            float bb0 = bias ? __ldg(bias + col) : 0.f;
            float bb1 = bias ? __ldg(bias + col + 1) : 0.f;
            float2 v0 = { acc[mi][j][0] + bb0, acc[mi][j][1] + bb1 };
            float2 v1 = { acc[mi][j][2] + bb0, acc[mi][j][3] + bb1 };
            *reinterpret_cast<float2*>(C + row0 * ldc + col)       = v0;
            *reinterpret_cast<float2*>(C + (row0 + 8) * ldc + col) = v1;
        }
    }
}

// ---------------- fp32 -> bf16 hi/lo split ----------------
__global__ void cvt_split(const float* __restrict__ src, __nv_bfloat16* __restrict__ hi,
                          __nv_bfloat16* __restrict__ lo, int n)
{
    int i = blockIdx.x * blockDim.x + threadIdx.x;
    if (i >= n) return;
    float x = src[i];
    __nv_bfloat16 h = __float2bfloat16(x);
    hi[i] = h;
    if (lo) lo[i] = __float2bfloat16(x - __bfloat162float(h));
}

// ---------------- RoPE (verified R2) ----------------
__global__ void rope_kernel(float* __restrict__ Qlin, float* __restrict__ Klin,
                            const float* __restrict__ cosv, const float* __restrict__ sinv)
{
    int idx = blockIdx.x * blockDim.x + threadIdx.x;
    const int total = TS * (THQ + THKV) * (TDH / 2);
    if (idx >= total) return;
    int d  = idx & 31;
    int hh = (idx >> 5) % (THQ + THKV);
    int s  = idx / ((THQ + THKV) * 32);
    float c  = cosv[s * 32 + d];
    float sn = sinv[s * 32 + d];
    float* p = (hh < THQ) ? (Qlin + (long)s * TQD + hh * TDH)
                          : (Klin + (long)s * TKD + (hh - THQ) * TDH);
    float x1 = p[d], x2 = p[d + 32];
    p[d]      = x1 * c - x2 * sn;
    p[d + 32] = x2 * c + x1 * sn;
}

// ---------------- softmax with sink (verified R2) ----------------
__global__ __launch_bounds__(256) void softmax_kernel(float* __restrict__ attn,
                                                      const float* __restrict__ sinks)
{
    int q = blockIdx.x, h = blockIdx.y;
    float* row = attn + ((long)h * TS + q) * TS;
    int t = threadIdx.x;
    __shared__ float red[256];

    float m = -3.0e38f;
    for (int k = t; k <= q; k += 256) m = fmaxf(m, row[k] * TSCALE);
    red[t] = m; __syncthreads();
    for (int s = 128; s > 0; s >>= 1) {
        if (t < s) red[t] = fmaxf(red[t], red[t + s]);
        __syncthreads();
    }
    float sink = sinks[h];
    float mx = fmaxf(red[0], sink);
    __syncthreads();

    float sum = 0.f;
    for (int k = t; k <= q; k += 256) sum += expf(row[k] * TSCALE - mx);
    red[t] = sum; __syncthreads();
    for (int s = 128; s > 0; s >>= 1) {
        if (t < s) red[t] += red[t + s];
        __syncthreads();
    }
    float inv = 1.f / (red[0] + expf(sink - mx));
    __syncthreads();

    for (int k = t; k < TS; k += 256)
        row[k] = (k <= q) ? expf(row[k] * TSCALE - mx) * inv : 0.f;
}

// ---------------- host ----------------
extern "C" void kernel_launch(void* const* d_in, const int* in_sizes, int n_in,
                              void* d_out, int out_size)
{
    (void)in_sizes; (void)n_in;
    const float* X     = (const float*)d_in[0];
    const float* cosv  = (const float*)d_in[2];
    const float* sinv  = (const float*)d_in[3];
    const float* Wq    = (const float*)d_in[4];
    const float* bq    = (const float*)d_in[5];
    const float* Wk    = (const float*)d_in[6];
    const float* bk    = (const float*)d_in[7];
    const float* Wv    = (const float*)d_in[8];
    const float* bv    = (const float*)d_in[9];
    const float* Wo    = (const float*)d_in[10];
    const float* bo    = (const float*)d_in[11];
    const float* sinks = (const float*)d_in[12];

    float *Qlin, *Klin, *Vlin, *Opre, *attnScr;
    __nv_bfloat16 *Xh, *Xl, *Wqh, *Wql, *Wkh, *Wkl, *Wvh, *Wvl, *Woh, *Wol, *Oh, *Ol;
    cudaGetSymbolAddress((void**)&Qlin, g_Qlin);
    cudaGetSymbolAddress((void**)&Klin, g_Klin);
    cudaGetSymbolAddress((void**)&Vlin, g_Vlin);
    cudaGetSymbolAddress((void**)&Opre, g_Opre);
    cudaGetSymbolAddress((void**)&attnScr, g_attn_scratch);
    cudaGetSymbolAddress((void**)&Xh, g_Xh);   cudaGetSymbolAddress((void**)&Xl, g_Xl);
    cudaGetSymbolAddress((void**)&Wqh, g_Wqh); cudaGetSymbolAddress((void**)&Wql, g_Wql);
    cudaGetSymbolAddress((void**)&Wkh, g_Wkh); cudaGetSymbolAddress((void**)&Wkl, g_Wkl);
    cudaGetSymbolAddress((void**)&Wvh, g_Wvh); cudaGetSymbolAddress((void**)&Wvl, g_Wvl);
    cudaGetSymbolAddress((void**)&Woh, g_Woh); cudaGetSymbolAddress((void**)&Wol, g_Wol);
    cudaGetSymbolAddress((void**)&Oh, g_Oh);   cudaGetSymbolAddress((void**)&Ol, g_Ol);

    float* out  = (float*)d_out;
    float* attn = ((long)out_size >= OUT_ELEMS + ATTN_ELEMS) ? (out + OUT_ELEMS) : attnScr;

    const int CT = 256;
    auto cgrid = [](long n) { return (unsigned)((n + 255) / 256); };
    dim3 blk(256);

    // splits for mma projections
    cvt_split<<<cgrid((long)TS * TDM),  CT>>>(X,  Xh,  Xl,  TS * TDM);
    cvt_split<<<cgrid((long)TQD * TDM), CT>>>(Wq, Wqh, Wql, TQD * TDM);
    cvt_split<<<cgrid((long)TKD * TDM), CT>>>(Wk, Wkh, Wkl, TKD * TDM);
    cvt_split<<<cgrid((long)TKD * TDM), CT>>>(Wv, Wvh, Wvl, TKD * TDM);
    cvt_split<<<cgrid((long)TDM * TQD), CT>>>(Wo, Woh, Wol, TDM * TQD);

    // QKV projections via mma (bf16x3)
    gemm_tc<<<dim3(TQD / 64, TS / 128, 1), 256>>>(
        Xh, Xl, Wqh, Wql, bq, Qlin, TDM, TDM, TDM, TQD, 0, 0, 0, 1, 3);
    gemm_tc<<<dim3(TKD / 64, TS / 128, 1), 256>>>(
        Xh, Xl, Wkh, Wkl, bk, Klin, TDM, TDM, TDM, TKD, 0, 0, 0, 1, 3);
    gemm_tc<<<dim3(TKD / 64, TS / 128, 1), 256>>>(
        Xh, Xl, Wvh, Wvl, bv, Vlin, TDM, TDM, TDM, TKD, 0, 0, 0, 1, 3);

    // RoPE
    {
        int np = TS * (THQ + THKV) * (TDH / 2);
        rope_kernel<<<(np + 255) / 256, 256>>>(Qlin, Klin, cosv, sinv);
    }

    // scores via verified FFMA (fp32): S[h][q][k] = Q_h[q,:] . K_kv[k,:]
    gemm_tiled<<<dim3(TS / 64, TS / 128, THQ), blk>>>(Qlin, Klin, nullptr, attn,
        TS, TS, TDH, TQD, TKD, TS,
        (long)TDH, (long)TDH, (long)TS * TS, TNREP, 1);

    // softmax with sink (fp32, verified)
    softmax_kernel<<<dim3(TS, THQ), 256>>>(attn, sinks);

    // attn @ V via verified FFMA (fp32, NN)
    gemm_tiled<<<dim3(TDH / 64, TS / 128, THQ), blk>>>(attn, Vlin, nullptr, Opre,
        TS, TDH, TS, TS, TKD, TQD,
        (long)TS * TS, (long)TDH, (long)TDH, TNREP, 0);

    // out-proj via mma (bf16x3)
    cvt_split<<<cgrid((long)TS * TQD), CT>>>(Opre, Oh, Ol, TS * TQD);
    gemm_tc<<<dim3(TDM / 64, TS / 128, 1), 256>>>(
        Oh, Ol, Woh, Wol, bo, out, TQD, TQD, TQD, TDM, 0, 0, 0, 1, 3);
}

// round 7
// speedup vs baseline: 2.4778x; 1.4614x over previous
#include <cuda_runtime.h>
#include <cuda_bf16.h>
#include <cstdint>
#include <cfloat>

// ---------------- problem constants ----------------
#define TS    1536
#define TDM   2880
#define THQ   64
#define THKV  8
#define TDH   64
#define TNREP 8
#define TQD   4096
#define TKD   512
#define TSCALE 0.125f

static const long OUT_ELEMS  = (long)TS * TDM;
static const long ATTN_ELEMS = (long)THQ * TS * TS;

// ---------------- device scratch (allocation-free) ----------------
__device__ __align__(1024) float g_Qlin[(size_t)TS * TQD];
__device__ __align__(1024) float g_Klin[(size_t)TS * TKD];
__device__ __align__(1024) float g_Vlin[(size_t)TS * TKD];
__device__ __align__(1024) float g_Opre[(size_t)TS * TQD];
__device__ __align__(1024) float g_attn_scratch[(size_t)THQ * TS * TS];

__device__ __align__(1024) __nv_bfloat16 g_Xh[(size_t)TS * TDM];
__device__ __align__(1024) __nv_bfloat16 g_Xl[(size_t)TS * TDM];
__device__ __align__(1024) __nv_bfloat16 g_Wqh[(size_t)TQD * TDM];
__device__ __align__(1024) __nv_bfloat16 g_Wql[(size_t)TQD * TDM];
__device__ __align__(1024) __nv_bfloat16 g_Wkh[(size_t)TKD * TDM];
__device__ __align__(1024) __nv_bfloat16 g_Wkl[(size_t)TKD * TDM];
__device__ __align__(1024) __nv_bfloat16 g_Wvh[(size_t)TKD * TDM];
__device__ __align__(1024) __nv_bfloat16 g_Wvl[(size_t)TKD * TDM];
__device__ __align__(1024) __nv_bfloat16 g_Woh[(size_t)TDM * TQD];
__device__ __align__(1024) __nv_bfloat16 g_Wol[(size_t)TDM * TQD];
__device__ __align__(1024) __nv_bfloat16 g_Qh[(size_t)TS * TQD];
__device__ __align__(1024) __nv_bfloat16 g_Kh[(size_t)TS * TKD];
__device__ __align__(1024) __nv_bfloat16 g_Vth[(size_t)TKD * TS];
__device__ __align__(1024) __nv_bfloat16 g_Vtl[(size_t)TKD * TS];
__device__ __align__(1024) __nv_bfloat16 g_Ph[(size_t)THQ * TS * TS];
__device__ __align__(1024) __nv_bfloat16 g_Pl[(size_t)THQ * TS * TS];
__device__ __align__(1024) __nv_bfloat16 g_Oh[(size_t)TS * TQD];
__device__ __align__(1024) __nv_bfloat16 g_Ol[(size_t)TS * TQD];

// ---------------- mma primitive ----------------
__device__ __forceinline__ void mma16816(float* d, const uint32_t* a, uint32_t b0, uint32_t b1) {
    asm volatile(
        "mma.sync.aligned.m16n8k16.row.col.f32.bf16.bf16.f32 "
        "{%0,%1,%2,%3}, {%4,%5,%6,%7}, {%8,%9}, {%0,%1,%2,%3};"
        : "+f"(d[0]), "+f"(d[1]), "+f"(d[2]), "+f"(d[3])
        : "r"(a[0]), "r"(a[1]), "r"(a[2]), "r"(a[3]), "r"(b0), "r"(b1));
}

// ---------------- tensor-core GEMM (verified core in R6 + z*sC fix) ----------------
// C[m,n] = sum_k A[m,k]*B[n,k] (+bias[n]); A [M,K], B [N,K] row-major bf16.
// nsplit==3: C = Ah*Bh + Ah*Bl + Al*Bh via 3-phase virtual k-loop.
// Tiles: BM=128, BN=64, BK=64; 256 threads (8 warps: 4x2, 32x32/warp).
#define SRP 72

__global__ __launch_bounds__(256)
void gemm_tc(const __nv_bfloat16* __restrict__ Ah, const __nv_bfloat16* __restrict__ Al,
             const __nv_bfloat16* __restrict__ Bh, const __nv_bfloat16* __restrict__ Bl,
             const float* __restrict__ bias, float* __restrict__ C,
             int K, int lda, int ldb, int ldc,
             long sA, long sB, long sC, int bGroup, int nsplit)
{
    __shared__ __align__(16) __nv_bfloat16 smA[128 * SRP];
    __shared__ __align__(16) __nv_bfloat16 smB[64 * SRP];

    const int z = blockIdx.z;
    C += (long)z * sC;                         // <-- the R4/R5 bug: this was missing
    const __nv_bfloat16* PA[3];
    const __nv_bfloat16* PB[3];
    {
        const __nv_bfloat16* ah = Ah + (long)z * sA;
        const __nv_bfloat16* bh = Bh + (long)(z / bGroup) * sB;
        const __nv_bfloat16* al = (nsplit == 3) ? (Al + (long)z * sA) : ah;
        const __nv_bfloat16* bl = (nsplit == 3) ? (Bl + (long)(z / bGroup) * sB) : bh;
        PA[0] = ah; PA[1] = ah; PA[2] = al;
        PB[0] = bh; PB[1] = bl; PB[2] = bh;
    }

    const int t    = threadIdx.x;
    const int lane = t & 31;
    const int w    = t >> 5;
    const int wm   = (w >> 1) * 32;
    const int wn   = (w & 1) * 32;
    const int g    = lane >> 2;
    const int tg   = lane & 3;
    const int m0   = blockIdx.y * 128;
    const int n0   = blockIdx.x * 64;

    const int ncK = K >> 6;
    const int nc  = ncK * nsplit;

    float acc[2][4][4];
#pragma unroll
    for (int i = 0; i < 2; i++)
#pragma unroll
        for (int j = 0; j < 4; j++)
#pragma unroll
            for (int e = 0; e < 4; e++) acc[i][j][e] = 0.f;

    uint4 va[4], vb[2];
    int kcL = 0, phL = 0;

    {
        const __nv_bfloat16* pa = PA[0];
        const __nv_bfloat16* pb = PB[0];
#pragma unroll
        for (int i = 0; i < 4; ++i) {
            int ch = t + 256 * i;
            va[i] = *reinterpret_cast<const uint4*>(pa + (long)(m0 + (ch >> 3)) * lda + (long)(ch & 7) * 8);
        }
#pragma unroll
        for (int j = 0; j < 2; ++j) {
            int ch = t + 256 * j;
            vb[j] = *reinterpret_cast<const uint4*>(pb + (long)(n0 + (ch >> 3)) * ldb + (long)(ch & 7) * 8);
        }
        if (++kcL == ncK) { kcL = 0; ++phL; }
    }

    for (int c = 0; c < nc; ++c) {
        __syncthreads();
#pragma unroll
        for (int i = 0; i < 4; ++i) {
            int ch = t + 256 * i;
            *reinterpret_cast<uint4*>(smA + (ch >> 3) * SRP + (ch & 7) * 8) = va[i];
        }
#pragma unroll
        for (int j = 0; j < 2; ++j) {
            int ch = t + 256 * j;
            *reinterpret_cast<uint4*>(smB + (ch >> 3) * SRP + (ch & 7) * 8) = vb[j];
        }
        __syncthreads();

        if (c + 1 < nc) {
            const __nv_bfloat16* pa = PA[phL];
            const __nv_bfloat16* pb = PB[phL];
            const long k0 = (long)kcL << 6;
#pragma unroll
            for (int i = 0; i < 4; ++i) {
                int ch = t + 256 * i;
                va[i] = *reinterpret_cast<const uint4*>(pa + (long)(m0 + (ch >> 3)) * lda + k0 + (long)(ch & 7) * 8);
            }
#pragma unroll
            for (int j = 0; j < 2; ++j) {
                int ch = t + 256 * j;
                vb[j] = *reinterpret_cast<const uint4*>(pb + (long)(n0 + (ch >> 3)) * ldb + k0 + (long)(ch & 7) * 8);
            }
            if (++kcL == ncK) { kcL = 0; ++phL; }
        }

#pragma unroll
        for (int ks = 0; ks < 4; ++ks) {
            const int kk = ks * 16;
            uint32_t a[2][4];
#pragma unroll
            for (int mi = 0; mi < 2; ++mi) {
                const __nv_bfloat16* p0 = smA + (wm + mi * 16 + g) * SRP + kk + tg * 2;
                a[mi][0] = *reinterpret_cast<const uint32_t*>(p0);
                a[mi][1] = *reinterpret_cast<const uint32_t*>(p0 + 8 * SRP);
                a[mi][2] = *reinterpret_cast<const uint32_t*>(p0 + 8);
                a[mi][3] = *reinterpret_cast<const uint32_t*>(p0 + 8 * SRP + 8);
            }
            uint32_t b0[4], b1[4];
#pragma unroll
            for (int j = 0; j < 4; ++j) {
                const __nv_bfloat16* p0 = smB + (wn + j * 8 + g) * SRP + kk + tg * 2;
                b0[j] = *reinterpret_cast<const uint32_t*>(p0);
                b1[j] = *reinterpret_cast<const uint32_t*>(p0 + 8);
            }
#pragma unroll
            for (int mi = 0; mi < 2; ++mi)
#pragma unroll
                for (int j = 0; j < 4; ++j)
                    mma16816(acc[mi][j], a[mi], b0[j], b1[j]);
        }
    }

#pragma unroll
    for (int mi = 0; mi < 2; ++mi) {
        long row0 = m0 + wm + mi * 16 + g;
#pragma unroll
        for (int j = 0; j < 4; ++j) {
            int col = n0 + wn + j * 8 + tg * 2;
            float bb0 = bias ? __ldg(bias + col) : 0.f;
            float bb1 = bias ? __ldg(bias + col + 1) : 0.f;
            float2 v0 = { acc[mi][j][0] + bb0, acc[mi][j][1] + bb1 };
            float2 v1 = { acc[mi][j][2] + bb0, acc[mi][j][3] + bb1 };
            *reinterpret_cast<float2*>(C + row0 * ldc + col)       = v0;
            *reinterpret_cast<float2*>(C + (row0 + 8) * ldc + col) = v1;
        }
    }
}

// ---------------- fp32 -> bf16 hi/lo split ----------------
__global__ void cvt_split(const float* __restrict__ src, __nv_bfloat16* __restrict__ hi,
                          __nv_bfloat16* __restrict__ lo, int n)
{
    int i = blockIdx.x * blockDim.x + threadIdx.x;
    if (i >= n) return;
    float x = src[i];
    __nv_bfloat16 h = __float2bfloat16(x);
    hi[i] = h;
    if (lo) lo[i] = __float2bfloat16(x - __bfloat162float(h));
}

// V [s][kv*64+d] -> Vt [kv*64+d][s], split
__global__ void cvt_vT(const float* __restrict__ V, __nv_bfloat16* __restrict__ hi,
                       __nv_bfloat16* __restrict__ lo)
{
    int i = blockIdx.x * blockDim.x + threadIdx.x;
    if (i >= TKD * TS) return;
    int d = i / TS, s = i % TS;
    float x = V[(long)s * TKD + d];
    __nv_bfloat16 h = __float2bfloat16(x);
    hi[i] = h;
    lo[i] = __float2bfloat16(x - __bfloat162float(h));
}

// ---------------- RoPE ----------------
__global__ void rope_kernel(float* __restrict__ Qlin, float* __restrict__ Klin,
                            const float* __restrict__ cosv, const float* __restrict__ sinv)
{
    int idx = blockIdx.x * blockDim.x + threadIdx.x;
    const int total = TS * (THQ + THKV) * (TDH / 2);
    if (idx >= total) return;
    int d  = idx & 31;
    int hh = (idx >> 5) % (THQ + THKV);
    int s  = idx / ((THQ + THKV) * 32);
    float c  = cosv[s * 32 + d];
    float sn = sinv[s * 32 + d];
    float* p = (hh < THQ) ? (Qlin + (long)s * TQD + hh * TDH)
                          : (Klin + (long)s * TKD + (hh - THQ) * TDH);
    float x1 = p[d], x2 = p[d + 32];
    p[d]      = x1 * c - x2 * sn;
    p[d + 32] = x2 * c + x1 * sn;
}

// ---------------- softmax with sink (single pass) + P->bf16 hi/lo ----------------
__global__ __launch_bounds__(256) void softmax_kernel(float* __restrict__ attn,
                                                      __nv_bfloat16* __restrict__ Ph,
                                                      __nv_bfloat16* __restrict__ Pl,
                                                      const float* __restrict__ sinks)
{
    const int q = blockIdx.x, h = blockIdx.y;
    const long base = ((long)h * TS + q) * TS;
    float* row = attn + base;
    const int t = threadIdx.x;
    __shared__ float red[256];

    float xv[6];
    float m = -FLT_MAX;
#pragma unroll
    for (int i = 0; i < 6; ++i) {
        int k = t + 256 * i;
        float v = row[k];
        xv[i] = (k <= q) ? v * TSCALE : -FLT_MAX;
        m = fmaxf(m, xv[i]);
    }
    red[t] = m; __syncthreads();
    for (int s = 128; s > 0; s >>= 1) {
        if (t < s) red[t] = fmaxf(red[t], red[t + s]);
        __syncthreads();
    }
    const float sink = sinks[h];
    const float mx = fmaxf(red[0], sink);
    __syncthreads();

    float sum = 0.f;
#pragma unroll
    for (int i = 0; i < 6; ++i) {
        int k = t + 256 * i;
        float e = (k <= q) ? __expf(xv[i] - mx) : 0.f;
        xv[i] = e;
        sum += e;
    }
    red[t] = sum; __syncthreads();
    for (int s = 128; s > 0; s >>= 1) {
        if (t < s) red[t] += red[t + s];
        __syncthreads();
    }
    const float inv = 1.f / (red[0] + __expf(sink - mx));

#pragma unroll
    for (int i = 0; i < 6; ++i) {
        int k = t + 256 * i;
        float p = xv[i] * inv;
        row[k] = p;
        __nv_bfloat16 hh = __float2bfloat16(p);
        Ph[base + k] = hh;
        Pl[base + k] = __float2bfloat16(p - __bfloat162float(hh));
    }
}

// ---------------- host ----------------
extern "C" void kernel_launch(void* const* d_in, const int* in_sizes, int n_in,
                              void* d_out, int out_size)
{
    (void)in_sizes; (void)n_in;
    const float* X     = (const float*)d_in[0];
    const float* cosv  = (const float*)d_in[2];
    const float* sinv  = (const float*)d_in[3];
    const float* Wq    = (const float*)d_in[4];
    const float* bq    = (const float*)d_in[5];
    const float* Wk    = (const float*)d_in[6];
    const float* bk    = (const float*)d_in[7];
    const float* Wv    = (const float*)d_in[8];
    const float* bv    = (const float*)d_in[9];
    const float* Wo    = (const float*)d_in[10];
    const float* bo    = (const float*)d_in[11];
    const float* sinks = (const float*)d_in[12];

    float *Qlin, *Klin, *Vlin, *Opre, *attnScr;
    __nv_bfloat16 *Xh, *Xl, *Wqh, *Wql, *Wkh, *Wkl, *Wvh, *Wvl, *Woh, *Wol;
    __nv_bfloat16 *Qh, *Kh, *Vth, *Vtl, *Ph, *Pl, *Oh, *Ol;
    cudaGetSymbolAddress((void**)&Qlin, g_Qlin);
    cudaGetSymbolAddress((void**)&Klin, g_Klin);
    cudaGetSymbolAddress((void**)&Vlin, g_Vlin);
    cudaGetSymbolAddress((void**)&Opre, g_Opre);
    cudaGetSymbolAddress((void**)&attnScr, g_attn_scratch);
    cudaGetSymbolAddress((void**)&Xh, g_Xh);   cudaGetSymbolAddress((void**)&Xl, g_Xl);
    cudaGetSymbolAddress((void**)&Wqh, g_Wqh); cudaGetSymbolAddress((void**)&Wql, g_Wql);
    cudaGetSymbolAddress((void**)&Wkh, g_Wkh); cudaGetSymbolAddress((void**)&Wkl, g_Wkl);
    cudaGetSymbolAddress((void**)&Wvh, g_Wvh); cudaGetSymbolAddress((void**)&Wvl, g_Wvl);
    cudaGetSymbolAddress((void**)&Woh, g_Woh); cudaGetSymbolAddress((void**)&Wol, g_Wol);
    cudaGetSymbolAddress((void**)&Qh, g_Qh);   cudaGetSymbolAddress((void**)&Kh, g_Kh);
    cudaGetSymbolAddress((void**)&Vth, g_Vth); cudaGetSymbolAddress((void**)&Vtl, g_Vtl);
    cudaGetSymbolAddress((void**)&Ph, g_Ph);   cudaGetSymbolAddress((void**)&Pl, g_Pl);
    cudaGetSymbolAddress((void**)&Oh, g_Oh);   cudaGetSymbolAddress((void**)&Ol, g_Ol);

    float* out  = (float*)d_out;
    float* attn = ((long)out_size >= OUT_ELEMS + ATTN_ELEMS) ? (out + OUT_ELEMS) : attnScr;

    const int CT = 256;
    auto cgrid = [](long n) { return (unsigned)((n + 255) / 256); };
    const __nv_bfloat16* nb = nullptr;
    const float* nf = nullptr;

    // split inputs/weights
    cvt_split<<<cgrid((long)TS * TDM),  CT>>>(X,  Xh,  Xl,  TS * TDM);
    cvt_split<<<cgrid((long)TQD * TDM), CT>>>(Wq, Wqh, Wql, TQD * TDM);
    cvt_split<<<cgrid((long)TKD * TDM), CT>>>(Wk, Wkh, Wkl, TKD * TDM);
    cvt_split<<<cgrid((long)TKD * TDM), CT>>>(Wv, Wvh, Wvl, TKD * TDM);
    cvt_split<<<cgrid((long)TDM * TQD), CT>>>(Wo, Woh, Wol, TDM * TQD);

    // QKV projections (bf16x3)
    gemm_tc<<<dim3(TQD / 64, TS / 128, 1), 256>>>(
        Xh, Xl, Wqh, Wql, bq, Qlin, TDM, TDM, TDM, TQD, 0, 0, 0, 1, 3);
    gemm_tc<<<dim3(TKD / 64, TS / 128, 1), 256>>>(
        Xh, Xl, Wkh, Wkl, bk, Klin, TDM, TDM, TDM, TKD, 0, 0, 0, 1, 3);
    gemm_tc<<<dim3(TKD / 64, TS / 128, 1), 256>>>(
        Xh, Xl, Wvh, Wvl, bv, Vlin, TDM, TDM, TDM, TKD, 0, 0, 0, 1, 3);

    // RoPE
    {
        int np = TS * (THQ + THKV) * (TDH / 2);
        rope_kernel<<<(np + 255) / 256, 256>>>(Qlin, Klin, cosv, sinv);
    }

    // Q/K -> bf16 hi (scores), V -> transposed hi/lo
    cvt_split<<<cgrid((long)TS * TQD), CT>>>(Qlin, Qh, (__nv_bfloat16*)nullptr, TS * TQD);
    cvt_split<<<cgrid((long)TS * TKD), CT>>>(Klin, Kh, (__nv_bfloat16*)nullptr, TS * TKD);
    cvt_vT<<<cgrid((long)TKD * TS), CT>>>(Vlin, Vth, Vtl);

    // scores (bf16 hi only): S[h][q][k] = Q_h[q,:] . K_kv[k,:]
    gemm_tc<<<dim3(TS / 64, TS / 128, THQ), 256>>>(
        Qh, nb, Kh, nb, nf, attn, TDH, TQD, TKD, TS,
        (long)TDH, (long)TDH, (long)TS * TS, TNREP, 1);

    // softmax + sink + P split
    softmax_kernel<<<dim3(TS, THQ), 256>>>(attn, Ph, Pl, sinks);

    // attn @ V (bf16x3): Opre[q][h*64+d] = sum_k P[h][q][k] * Vt[d][k]
    gemm_tc<<<dim3(1, TS / 128, THQ), 256>>>(
        Ph, Pl, Vth, Vtl, nf, Opre, TS, TS, TS, TQD,
        (long)TS * TS, (long)TDH * TS, (long)TDH, TNREP, 3);

    // Opre -> bf16 split
    cvt_split<<<cgrid((long)TS * TQD), CT>>>(Opre, Oh, Ol, TS * TQD);

    // out projection (bf16x3)
    gemm_tc<<<dim3(TDM / 64, TS / 128, 1), 256>>>(
        Oh, Ol, Woh, Wol, bo, out, TQD, TQD, TQD, TDM, 0, 0, 0, 1, 3);
}

// round 8
// speedup vs baseline: 3.0351x; 1.2249x over previous
#include <cuda_runtime.h>
#include <cuda_bf16.h>
#include <cstdint>
#include <cfloat>

// ---------------- problem constants ----------------
#define TS    1536
#define TDM   2880
#define THQ   64
#define THKV  8
#define TDH   64
#define TNREP 8
#define TQD   4096
#define TKD   512
#define TSCALE 0.125f

static const long OUT_ELEMS  = (long)TS * TDM;
static const long ATTN_ELEMS = (long)THQ * TS * TS;

// ---------------- device scratch (allocation-free) ----------------
__device__ __align__(1024) float g_Qlin[(size_t)TS * TQD];
__device__ __align__(1024) float g_Klin[(size_t)TS * TKD];
__device__ __align__(1024) float g_Vlin[(size_t)TS * TKD];
__device__ __align__(1024) float g_Opre[(size_t)TS * TQD];
__device__ __align__(1024) float g_attn_scratch[(size_t)THQ * TS * TS];

__device__ __align__(1024) __nv_bfloat16 g_Xh[(size_t)TS * TDM];
__device__ __align__(1024) __nv_bfloat16 g_Xl[(size_t)TS * TDM];
__device__ __align__(1024) __nv_bfloat16 g_Wqh[(size_t)TQD * TDM];
__device__ __align__(1024) __nv_bfloat16 g_Wql[(size_t)TQD * TDM];
__device__ __align__(1024) __nv_bfloat16 g_Wkh[(size_t)TKD * TDM];
__device__ __align__(1024) __nv_bfloat16 g_Wkl[(size_t)TKD * TDM];
__device__ __align__(1024) __nv_bfloat16 g_Wvh[(size_t)TKD * TDM];
__device__ __align__(1024) __nv_bfloat16 g_Wvl[(size_t)TKD * TDM];
__device__ __align__(1024) __nv_bfloat16 g_Woh[(size_t)TDM * TQD];
__device__ __align__(1024) __nv_bfloat16 g_Wol[(size_t)TDM * TQD];
__device__ __align__(1024) __nv_bfloat16 g_Qh[(size_t)TS * TQD];
__device__ __align__(1024) __nv_bfloat16 g_Kh[(size_t)TS * TKD];
__device__ __align__(1024) __nv_bfloat16 g_Vth[(size_t)TKD * TS];
__device__ __align__(1024) __nv_bfloat16 g_Vtl[(size_t)TKD * TS];
__device__ __align__(1024) __nv_bfloat16 g_Ph[(size_t)THQ * TS * TS];
__device__ __align__(1024) __nv_bfloat16 g_Pl[(size_t)THQ * TS * TS];
__device__ __align__(1024) __nv_bfloat16 g_Oh[(size_t)TS * TQD];
__device__ __align__(1024) __nv_bfloat16 g_Ol[(size_t)TS * TQD];

// ---------------- primitives ----------------
__device__ __forceinline__ uint32_t smem_u32(const void* p) {
    uint32_t a;
    asm("{ .reg .u64 t; cvta.to.shared.u64 t, %1; cvt.u32.u64 %0, t; }" : "=r"(a) : "l"(p));
    return a;
}
__device__ __forceinline__ void cp16(uint32_t dst, const void* src) {
    asm volatile("cp.async.cg.shared.global [%0], [%1], 16;" :: "r"(dst), "l"(src) : "memory");
}
__device__ __forceinline__ void cp_commit() {
    asm volatile("cp.async.commit_group;" ::: "memory");
}
__device__ __forceinline__ void cp_wait1() {
    asm volatile("cp.async.wait_group 1;" ::: "memory");
}
__device__ __forceinline__ void cp_wait0() {
    asm volatile("cp.async.wait_group 0;" ::: "memory");
}
__device__ __forceinline__ void mma16816(float* d, const uint32_t* a, uint32_t b0, uint32_t b1) {
    asm volatile(
        "mma.sync.aligned.m16n8k16.row.col.f32.bf16.bf16.f32 "
        "{%0,%1,%2,%3}, {%4,%5,%6,%7}, {%8,%9}, {%0,%1,%2,%3};"
        : "+f"(d[0]), "+f"(d[1]), "+f"(d[2]), "+f"(d[3])
        : "r"(a[0]), "r"(a[1]), "r"(a[2]), "r"(a[3]), "r"(b0), "r"(b1));
}

// ---------------- tensor-core GEMM (verified fragment path + cp.async pipe) ----
// C[m,n] = sum_k A[m,k]*B[n,k] (+bias[n]); A [M,K], B [N,K] row-major bf16.
// nsplit==3: C = Ah*Bh + Ah*Bl + Al*Bh via 3-phase virtual k-loop.
// Tiles: BM=128, BN=64, BK=64; 256 threads (8 warps: 4x2, 32x32/warp).
// causal: 0 none; 1 = limit K to m0+128 (attn@V); 2 = skip blocks above diag (scores).
#define SRP   72                     // smem row pitch in bf16 elems (144 B)
#define SRPB  144
#define ABYTES (128 * SRPB)          // 18432
#define BUFB  (ABYTES + 64 * SRPB)   // 27648 per stage
#define GEMM_SMEM (2 * BUFB)         // 55296

__global__ __launch_bounds__(256)
void gemm_tc(const __nv_bfloat16* __restrict__ Ah, const __nv_bfloat16* __restrict__ Al,
             const __nv_bfloat16* __restrict__ Bh, const __nv_bfloat16* __restrict__ Bl,
             const float* __restrict__ bias, float* __restrict__ C,
             int K, int lda, int ldb, int ldc,
             long sA, long sB, long sC, int bGroup, int nsplit, int causal)
{
    extern __shared__ __align__(16) char smem[];
    const uint32_t su = smem_u32(smem);

    const int m0 = blockIdx.y * 128;
    const int n0 = blockIdx.x * 64;
    if (causal == 2 && n0 >= m0 + 128) return;   // fully-masked score block

    if (causal == 1) { int ke = m0 + 128; if (ke < K) K = ke; }

    const int z = blockIdx.z;
    C += (long)z * sC;
    const __nv_bfloat16* PA[3];
    const __nv_bfloat16* PB[3];
    {
        const __nv_bfloat16* ah = Ah + (long)z * sA;
        const __nv_bfloat16* bh = Bh + (long)(z / bGroup) * sB;
        const __nv_bfloat16* al = (nsplit == 3) ? (Al + (long)z * sA) : ah;
        const __nv_bfloat16* bl = (nsplit == 3) ? (Bl + (long)(z / bGroup) * sB) : bh;
        PA[0] = ah; PA[1] = ah; PA[2] = al;
        PB[0] = bh; PB[1] = bl; PB[2] = bh;
    }

    const int t    = threadIdx.x;
    const int lane = t & 31;
    const int w    = t >> 5;
    const int wm   = (w >> 1) * 32;
    const int wn   = (w & 1) * 32;
    const int g    = lane >> 2;
    const int tg   = lane & 3;

    const int ncK = K >> 6;
    const int nc  = ncK * nsplit;

    float acc[2][4][4];
#pragma unroll
    for (int i = 0; i < 2; i++)
#pragma unroll
        for (int j = 0; j < 4; j++)
#pragma unroll
            for (int e = 0; e < 4; e++) acc[i][j][e] = 0.f;

    auto issue = [&](int c, int buf) {
        int ph = 0, kc = c;
        while (kc >= ncK) { kc -= ncK; ++ph; }
        const __nv_bfloat16* pa = PA[ph];
        const __nv_bfloat16* pb = PB[ph];
        const long k0 = (long)kc << 6;
        const uint32_t sa = su + buf * BUFB;
        const uint32_t sb = sa + ABYTES;
#pragma unroll
        for (int i = 0; i < 4; ++i) {
            int ch = t + 256 * i;                       // 0..1023: row=ch>>3, c16=ch&7
            cp16(sa + (uint32_t)(ch >> 3) * SRPB + (uint32_t)(ch & 7) * 16,
                 pa + (long)(m0 + (ch >> 3)) * lda + k0 + (long)(ch & 7) * 8);
        }
#pragma unroll
        for (int j = 0; j < 2; ++j) {
            int ch = t + 256 * j;                       // 0..511
            cp16(sb + (uint32_t)(ch >> 3) * SRPB + (uint32_t)(ch & 7) * 16,
                 pb + (long)(n0 + (ch >> 3)) * ldb + k0 + (long)(ch & 7) * 8);
        }
        cp_commit();
    };

    issue(0, 0);

    for (int c = 0; c < nc; ++c) {
        const int buf = c & 1;
        if (c + 1 < nc) { issue(c + 1, buf ^ 1); cp_wait1(); }
        else            { cp_wait0(); }
        __syncthreads();

        const __nv_bfloat16* smA = reinterpret_cast<const __nv_bfloat16*>(smem + buf * BUFB);
        const __nv_bfloat16* smB = reinterpret_cast<const __nv_bfloat16*>(smem + buf * BUFB + ABYTES);

#pragma unroll
        for (int ks = 0; ks < 4; ++ks) {
            const int kk = ks * 16;
            uint32_t a[2][4];
#pragma unroll
            for (int mi = 0; mi < 2; ++mi) {
                const __nv_bfloat16* p0 = smA + (wm + mi * 16 + g) * SRP + kk + tg * 2;
                a[mi][0] = *reinterpret_cast<const uint32_t*>(p0);
                a[mi][1] = *reinterpret_cast<const uint32_t*>(p0 + 8 * SRP);
                a[mi][2] = *reinterpret_cast<const uint32_t*>(p0 + 8);
                a[mi][3] = *reinterpret_cast<const uint32_t*>(p0 + 8 * SRP + 8);
            }
            uint32_t b0[4], b1[4];
#pragma unroll
            for (int j = 0; j < 4; ++j) {
                const __nv_bfloat16* p0 = smB + (wn + j * 8 + g) * SRP + kk + tg * 2;
                b0[j] = *reinterpret_cast<const uint32_t*>(p0);
                b1[j] = *reinterpret_cast<const uint32_t*>(p0 + 8);
            }
#pragma unroll
            for (int mi = 0; mi < 2; ++mi)
#pragma unroll
                for (int j = 0; j < 4; ++j)
                    mma16816(acc[mi][j], a[mi], b0[j], b1[j]);
        }
        __syncthreads();
    }

#pragma unroll
    for (int mi = 0; mi < 2; ++mi) {
        long row0 = m0 + wm + mi * 16 + g;
#pragma unroll
        for (int j = 0; j < 4; ++j) {
            int col = n0 + wn + j * 8 + tg * 2;
            float bb0 = bias ? __ldg(bias + col) : 0.f;
            float bb1 = bias ? __ldg(bias + col + 1) : 0.f;
            float2 v0 = { acc[mi][j][0] + bb0, acc[mi][j][1] + bb1 };
            float2 v1 = { acc[mi][j][2] + bb0, acc[mi][j][3] + bb1 };
            *reinterpret_cast<float2*>(C + row0 * ldc + col)       = v0;
            *reinterpret_cast<float2*>(C + (row0 + 8) * ldc + col) = v1;
        }
    }
}

// ---------------- fp32 -> bf16 hi/lo split ----------------
__global__ void cvt_split(const float* __restrict__ src, __nv_bfloat16* __restrict__ hi,
                          __nv_bfloat16* __restrict__ lo, int n)
{
    int i = blockIdx.x * blockDim.x + threadIdx.x;
    if (i >= n) return;
    float x = src[i];
    __nv_bfloat16 h = __float2bfloat16(x);
    hi[i] = h;
    if (lo) lo[i] = __float2bfloat16(x - __bfloat162float(h));
}

// V [s][kv*64+d] -> Vt [kv*64+d][s], split
__global__ void cvt_vT(const float* __restrict__ V, __nv_bfloat16* __restrict__ hi,
                       __nv_bfloat16* __restrict__ lo)
{
    int i = blockIdx.x * blockDim.x + threadIdx.x;
    if (i >= TKD * TS) return;
    int d = i / TS, s = i % TS;
    float x = V[(long)s * TKD + d];
    __nv_bfloat16 h = __float2bfloat16(x);
    hi[i] = h;
    lo[i] = __float2bfloat16(x - __bfloat162float(h));
}

// ---------------- RoPE ----------------
__global__ void rope_kernel(float* __restrict__ Qlin, float* __restrict__ Klin,
                            const float* __restrict__ cosv, const float* __restrict__ sinv)
{
    int idx = blockIdx.x * blockDim.x + threadIdx.x;
    const int total = TS * (THQ + THKV) * (TDH / 2);
    if (idx >= total) return;
    int d  = idx & 31;
    int hh = (idx >> 5) % (THQ + THKV);
    int s  = idx / ((THQ + THKV) * 32);
    float c  = cosv[s * 32 + d];
    float sn = sinv[s * 32 + d];
    float* p = (hh < THQ) ? (Qlin + (long)s * TQD + hh * TDH)
                          : (Klin + (long)s * TKD + (hh - THQ) * TDH);
    float x1 = p[d], x2 = p[d + 32];
    p[d]      = x1 * c - x2 * sn;
    p[d + 32] = x2 * c + x1 * sn;
}

// ---------------- softmax with sink + P split (causal-trimmed traffic) ----------
__global__ __launch_bounds__(256) void softmax_kernel(float* __restrict__ attn,
                                                      __nv_bfloat16* __restrict__ Ph,
                                                      __nv_bfloat16* __restrict__ Pl,
                                                      const float* __restrict__ sinks)
{
    const int q = blockIdx.x, h = blockIdx.y;
    const long base = ((long)h * TS + q) * TS;
    float* row = attn + base;
    const int t = threadIdx.x;
    const int qbound = ((q >> 7) + 1) << 7;   // 128-aligned causal bound (what attn@V reads)
    __shared__ float red[256];

    float xv[6];
    float m = -FLT_MAX;
#pragma unroll
    for (int i = 0; i < 6; ++i) {
        int k = t + 256 * i;
        xv[i] = (k <= q) ? row[k] * TSCALE : -FLT_MAX;   // no read when masked
        m = fmaxf(m, xv[i]);
    }
    red[t] = m; __syncthreads();
    for (int s = 128; s > 0; s >>= 1) {
        if (t < s) red[t] = fmaxf(red[t], red[t + s]);
        __syncthreads();
    }
    const float sink = sinks[h];
    const float mx = fmaxf(red[0], sink);
    __syncthreads();

    float sum = 0.f;
#pragma unroll
    for (int i = 0; i < 6; ++i) {
        int k = t + 256 * i;
        float e = (k <= q) ? __expf(xv[i] - mx) : 0.f;
        xv[i] = e;
        sum += e;
    }
    red[t] = sum; __syncthreads();
    for (int s = 128; s > 0; s >>= 1) {
        if (t < s) red[t] += red[t + s];
        __syncthreads();
    }
    const float inv = 1.f / (red[0] + __expf(sink - mx));

#pragma unroll
    for (int i = 0; i < 6; ++i) {
        int k = t + 256 * i;
        float p = xv[i] * inv;
        row[k] = p;                               // full row (attn output incl. zeros)
        if (k < qbound) {                         // P split only where attn@V reads
            __nv_bfloat16 hh = __float2bfloat16(p);
            Ph[base + k] = hh;
            Pl[base + k] = __float2bfloat16(p - __bfloat162float(hh));
        }
    }
}

// ---------------- host ----------------
extern "C" void kernel_launch(void* const* d_in, const int* in_sizes, int n_in,
                              void* d_out, int out_size)
{
    (void)in_sizes; (void)n_in;
    const float* X     = (const float*)d_in[0];
    const float* cosv  = (const float*)d_in[2];
    const float* sinv  = (const float*)d_in[3];
    const float* Wq    = (const float*)d_in[4];
    const float* bq    = (const float*)d_in[5];
    const float* Wk    = (const float*)d_in[6];
    const float* bk    = (const float*)d_in[7];
    const float* Wv    = (const float*)d_in[8];
    const float* bv    = (const float*)d_in[9];
    const float* Wo    = (const float*)d_in[10];
    const float* bo    = (const float*)d_in[11];
    const float* sinks = (const float*)d_in[12];

    float *Qlin, *Klin, *Vlin, *Opre, *attnScr;
    __nv_bfloat16 *Xh, *Xl, *Wqh, *Wql, *Wkh, *Wkl, *Wvh, *Wvl, *Woh, *Wol;
    __nv_bfloat16 *Qh, *Kh, *Vth, *Vtl, *Ph, *Pl, *Oh, *Ol;
    cudaGetSymbolAddress((void**)&Qlin, g_Qlin);
    cudaGetSymbolAddress((void**)&Klin, g_Klin);
    cudaGetSymbolAddress((void**)&Vlin, g_Vlin);
    cudaGetSymbolAddress((void**)&Opre, g_Opre);
    cudaGetSymbolAddress((void**)&attnScr, g_attn_scratch);
    cudaGetSymbolAddress((void**)&Xh, g_Xh);   cudaGetSymbolAddress((void**)&Xl, g_Xl);
    cudaGetSymbolAddress((void**)&Wqh, g_Wqh); cudaGetSymbolAddress((void**)&Wql, g_Wql);
    cudaGetSymbolAddress((void**)&Wkh, g_Wkh); cudaGetSymbolAddress((void**)&Wkl, g_Wkl);
    cudaGetSymbolAddress((void**)&Wvh, g_Wvh); cudaGetSymbolAddress((void**)&Wvl, g_Wvl);
    cudaGetSymbolAddress((void**)&Woh, g_Woh); cudaGetSymbolAddress((void**)&Wol, g_Wol);
    cudaGetSymbolAddress((void**)&Qh, g_Qh);   cudaGetSymbolAddress((void**)&Kh, g_Kh);
    cudaGetSymbolAddress((void**)&Vth, g_Vth); cudaGetSymbolAddress((void**)&Vtl, g_Vtl);
    cudaGetSymbolAddress((void**)&Ph, g_Ph);   cudaGetSymbolAddress((void**)&Pl, g_Pl);
    cudaGetSymbolAddress((void**)&Oh, g_Oh);   cudaGetSymbolAddress((void**)&Ol, g_Ol);

    float* out  = (float*)d_out;
    float* attn = ((long)out_size >= OUT_ELEMS + ATTN_ELEMS) ? (out + OUT_ELEMS) : attnScr;

    cudaFuncSetAttribute(gemm_tc, cudaFuncAttributeMaxDynamicSharedMemorySize, GEMM_SMEM);

    const int CT = 256;
    auto cgrid = [](long n) { return (unsigned)((n + 255) / 256); };
    const __nv_bfloat16* nb = nullptr;
    const float* nf = nullptr;

    // split inputs/weights
    cvt_split<<<cgrid((long)TS * TDM),  CT>>>(X,  Xh,  Xl,  TS * TDM);
    cvt_split<<<cgrid((long)TQD * TDM), CT>>>(Wq, Wqh, Wql, TQD * TDM);
    cvt_split<<<cgrid((long)TKD * TDM), CT>>>(Wk, Wkh, Wkl, TKD * TDM);
    cvt_split<<<cgrid((long)TKD * TDM), CT>>>(Wv, Wvh, Wvl, TKD * TDM);
    cvt_split<<<cgrid((long)TDM * TQD), CT>>>(Wo, Woh, Wol, TDM * TQD);

    // QKV projections (bf16x3)
    gemm_tc<<<dim3(TQD / 64, TS / 128, 1), 256, GEMM_SMEM>>>(
        Xh, Xl, Wqh, Wql, bq, Qlin, TDM, TDM, TDM, TQD, 0, 0, 0, 1, 3, 0);
    gemm_tc<<<dim3(TKD / 64, TS / 128, 1), 256, GEMM_SMEM>>>(
        Xh, Xl, Wkh, Wkl, bk, Klin, TDM, TDM, TDM, TKD, 0, 0, 0, 1, 3, 0);
    gemm_tc<<<dim3(TKD / 64, TS / 128, 1), 256, GEMM_SMEM>>>(
        Xh, Xl, Wvh, Wvl, bv, Vlin, TDM, TDM, TDM, TKD, 0, 0, 0, 1, 3, 0);

    // RoPE
    {
        int np = TS * (THQ + THKV) * (TDH / 2);
        rope_kernel<<<(np + 255) / 256, 256>>>(Qlin, Klin, cosv, sinv);
    }

    // Q/K -> bf16 hi (scores), V -> transposed hi/lo
    cvt_split<<<cgrid((long)TS * TQD), CT>>>(Qlin, Qh, (__nv_bfloat16*)nullptr, TS * TQD);
    cvt_split<<<cgrid((long)TS * TKD), CT>>>(Klin, Kh, (__nv_bfloat16*)nullptr, TS * TKD);
    cvt_vT<<<cgrid((long)TKD * TS), CT>>>(Vlin, Vth, Vtl);

    // scores (bf16 hi only, skip fully-masked blocks)
    gemm_tc<<<dim3(TS / 64, TS / 128, THQ), 256, GEMM_SMEM>>>(
        Qh, nb, Kh, nb, nf, attn, TDH, TQD, TKD, TS,
        (long)TDH, (long)TDH, (long)TS * TS, TNREP, 1, 2);

    // softmax + sink + P split (trimmed)
    softmax_kernel<<<dim3(TS, THQ), 256>>>(attn, Ph, Pl, sinks);

    // attn @ V (bf16x3, causal k-limit per block-row)
    gemm_tc<<<dim3(1, TS / 128, THQ), 256, GEMM_SMEM>>>(
        Ph, Pl, Vth, Vtl, nf, Opre, TS, TS, TS, TQD,
        (long)TS * TS, (long)TDH * TS, (long)TDH, TNREP, 3, 1);

    // Opre -> bf16 split
    cvt_split<<<cgrid((long)TS * TQD), CT>>>(Opre, Oh, Ol, TS * TQD);

    // out projection (bf16x3)
    gemm_tc<<<dim3(TDM / 64, TS / 128, 1), 256, GEMM_SMEM>>>(
        Oh, Ol, Woh, Wol, bo, out, TQD, TQD, TQD, TDM, 0, 0, 0, 1, 3, 0);
}